// round 15
// baseline (speedup 1.0000x reference)
#include <cuda_runtime.h>
#include <cuda_fp16.h>
#include <cstdint>

// ---------------- problem constants ----------------
#define IMAGE_TOKEN 32000
constexpr int BB    = 8;
constexpr int SS    = 1024;
constexpr int DD    = 4096;
constexpr int DV    = 1024;
constexpr int KP1   = 640;     // 588 padded to mult of 64
constexpr int NP    = 576;
constexpr int MAXE  = 1599;
constexpr int MTOT  = 4608;    // B*NP

constexpr long long EMB_OFF = 1;
constexpr long long ATT_OFF = EMB_OFF + (long long)BB*MAXE*DD;
constexpr long long LAB_OFF = ATT_OFF + (long long)BB*MAXE;
constexpr long long RL_OFF  = LAB_OFF + (long long)BB*MAXE;
constexpr long long TOTAL   = RL_OFF + 32LL*MAXE*8 + 32LL*MAXE*2;

// ---------------- scratch (device globals) ----------------
__device__ __half g_xh[(size_t)MTOT*KP1];
__device__ __half g_hh[(size_t)MTOT*DV];
__device__ __half g_th[(size_t)MTOT*DD];
__device__ int    g_sidx[BB];
__device__ __half g_pwt_hi[(size_t)DV*KP1];
__device__ __half g_w1t_hi[(size_t)DD*DV];
__device__ __half g_w2t_hi[(size_t)DD*DD];

// ---------------- helpers ----------------
__device__ __forceinline__ uint32_t smem_u32(const void* p) {
    uint32_t a;
    asm("{ .reg .u64 t; cvta.to.shared.u64 t, %1; cvt.u32.u64 %0, t; }" : "=r"(a) : "l"(p));
    return a;
}
__device__ __forceinline__ float gelu_tanh(float x) {
    float x3 = x*x*x;
    return 0.5f*x*(1.0f + tanhf(0.7978845608028654f*(x + 0.044715f*x3)));
}

#define CP_ASYNC16(dst, src) \
    asm volatile("cp.async.cg.shared.global [%0], [%1], 16;" :: "r"(dst), "l"(src))
#define CP_COMMIT() asm volatile("cp.async.commit_group;")

template<int N>
__device__ __forceinline__ void cp_wait() {
    asm volatile("cp.async.wait_group %0;" :: "n"(N));
}

__device__ __forceinline__ void ldsm_x4(uint32_t* r, uint32_t addr) {
    asm volatile("ldmatrix.sync.aligned.m8n8.x4.shared.b16 {%0,%1,%2,%3}, [%4];"
        : "=r"(r[0]), "=r"(r[1]), "=r"(r[2]), "=r"(r[3]) : "r"(addr));
}
// non-volatile — pure register op; compiler may interleave
__device__ __forceinline__ void mma_f16(float* d, const uint32_t* a, const uint32_t* b) {
    asm("mma.sync.aligned.m16n8k16.row.col.f32.f16.f16.f32 "
        "{%0,%1,%2,%3}, {%4,%5,%6,%7}, {%8,%9}, {%0,%1,%2,%3};"
        : "+f"(d[0]), "+f"(d[1]), "+f"(d[2]), "+f"(d[3])
        : "r"(a[0]), "r"(a[1]), "r"(a[2]), "r"(a[3]), "r"(b[0]), "r"(b[1]));
}

constexpr int KCH  = 64;
constexpr int ROWB = KCH * 2;           // 128 B per smem row
constexpr int ARR  = 128 * ROWB;        // 16384 B per 128-row operand array

__device__ __forceinline__ uint32_t swz(int row, int ch) {
    return (uint32_t)(row * ROWB + ((ch ^ (row & 7)) << 4));
}

// ---------------- misc kernels ----------------
__global__ void find_sidx_kernel(const int* __restrict__ ids) {
    __shared__ int sm;
    if (threadIdx.x == 0) sm = SS;
    __syncthreads();
    int b = blockIdx.x;
    for (int t = threadIdx.x; t < SS; t += blockDim.x)
        if (ids[b*SS + t] == IMAGE_TOKEN) atomicMin(&sm, t);
    __syncthreads();
    if (threadIdx.x == 0) g_sidx[b] = sm;
}

__global__ void patchify_kernel(const float* __restrict__ px) {
    int idx = blockIdx.x*blockDim.x + threadIdx.x;
    if (idx >= MTOT*KP1) return;
    int m = idx / KP1, k = idx - m*KP1;
    float v = 0.0f;
    if (k < 588) {
        int b = m / NP, patch = m - b*NP;
        int gi = patch / 24, gj = patch - gi*24;
        int c = k / 196, r = k - c*196;
        int pi = r / 14, pj = r - pi*14;
        v = px[ (((size_t)(b*3 + c)*336) + gi*14 + pi) * 336 + gj*14 + pj ];
    }
    g_xh[idx] = __float2half_rn(v);
}

// fused transpose of all three weight matrices -> hi-only fp16, (N, Kp) layout
__global__ void transpose_all_kernel(const float* __restrict__ pw,
                                     const float* __restrict__ w1,
                                     const float* __restrict__ w2)
{
    int b = blockIdx.x;
    const float* W; __half* T; int K, N, Kp, kb;
    if (b < 640)       { W = pw; T = g_pwt_hi; K = 588; N = DV; Kp = KP1; kb = 20; }
    else if (b < 4736) { b -= 640;  W = w1; T = g_w1t_hi; K = DV; N = DD; Kp = DV; kb = 32; }
    else               { b -= 4736; W = w2; T = g_w2t_hi; K = DD; N = DD; Kp = DD; kb = 128; }
    int k0 = (b % kb) * 32, n0 = (b / kb) * 32;

    __shared__ float tile[32][33];
    int tx = threadIdx.x, ty = threadIdx.y;
    #pragma unroll
    for (int i = 0; i < 4; i++) {
        int k = k0 + ty + i*8;
        tile[ty + i*8][tx] = (k < K) ? W[(size_t)k*N + n0 + tx] : 0.0f;
    }
    __syncthreads();
    #pragma unroll
    for (int i = 0; i < 4; i++) {
        int n = n0 + ty + i*8;
        T[(size_t)n*Kp + k0 + tx] = __float2half_rn(tile[tx][ty + i*8]);
    }
}

// ---------------- 1-pass fp16 GEMM: CTA 128x128, 256 thr, warp 64x32, 2 CTAs/SM --------
// 3-stage cp.async pipeline (stage = Ah 16K | Bh 16K)
// mainloop: per k32 half, load 12 fragments upfront then fire 32 MMAs (2-pass issue shape)
// EPI: 0 = +bias -> f16 ; 1 = gelu(+bias) -> f16 ; 2 = +bias fp32 scatter to d_out
constexpr int STAGE1 = 2 * ARR;         // 32768
constexpr int GS1    = 3 * STAGE1;      // 98304

template<int EPI>
__global__ __launch_bounds__(256, 2)
void gemm_mma1(const __half* __restrict__ Ah, const __half* __restrict__ Bh,
               const float* __restrict__ bias,
               float* __restrict__ Cf, __half* __restrict__ Oh,
               int Kp, int Nout)
{
    extern __shared__ char smem[];
    const uint32_t sbase = smem_u32(smem);
    const int tid = threadIdx.x, wid = tid >> 5, lane = tid & 31;
    const int m0 = blockIdx.y * 128, n0 = blockIdx.x * 128;
    const int wm = wid >> 2, wn = wid & 3;     // warp grid 2x4, warp tile 64x32

    const int KT = Kp / KCH;

    auto fill = [&](int slot, int k0) {
        uint32_t stb = sbase + slot * STAGE1;
        #pragma unroll
        for (int u = 0; u < 4; u++) {
            int c = tid*4 + u;                 // 0..1023
            int row = c >> 3, ch = c & 7;
            uint32_t so = swz(row, ch);
            CP_ASYNC16(stb + so,       Ah + (size_t)(m0 + row)*Kp + k0 + ch*8);
            CP_ASYNC16(stb + ARR + so, Bh + (size_t)(n0 + row)*Kp + k0 + ch*8);
        }
    };

    float acc[4][4][4];
    #pragma unroll
    for (int i = 0; i < 4; i++)
        #pragma unroll
        for (int j = 0; j < 4; j++)
            #pragma unroll
            for (int r = 0; r < 4; r++) acc[i][j][r] = 0.0f;

    // per-lane ldmatrix address components (non-trans; operands stored k-contiguous)
    const int j8 = lane & 7, i4 = lane >> 3;
    const int arow_in = ((i4 & 1) << 3) + j8, achsel = i4 >> 1;
    const int brow_in = ((i4 >> 1) << 3) + j8, bchsel = i4 & 1;

    fill(0, 0); CP_COMMIT();
    fill(1, KCH); CP_COMMIT();

    for (int ks = 0; ks < KT; ks++) {
        cp_wait<1>();
        __syncthreads();
        uint32_t stb = sbase + (ks % 3) * STAGE1;

        #pragma unroll
        for (int half = 0; half < 2; half++) {
            // load ALL 12 fragments for this k32 half (2 k16 groups)
            uint32_t ah[2][4][4], bhf[2][8];
            #pragma unroll
            for (int sub = 0; sub < 2; sub++) {
                int g = half*2 + sub;
                #pragma unroll
                for (int i = 0; i < 4; i++) {
                    int row = wm*64 + i*16 + arow_in;
                    ldsm_x4(ah[sub][i], stb + swz(row, 2*g + achsel));
                }
                #pragma unroll
                for (int jp = 0; jp < 2; jp++) {
                    int row = wn*32 + jp*16 + brow_in;
                    ldsm_x4(bhf[sub] + jp*4, stb + ARR + swz(row, 2*g + bchsel));
                }
            }
            // overlap next-stage fill with ldsm latency (once per chunk)
            if (half == 0) {
                int ns = ks + 2;
                if (ns < KT) { fill(ns % 3, ns * KCH); CP_COMMIT(); }
            }
            // 32 MMAs: two independent 16-MMA sets
            #pragma unroll
            for (int sub = 0; sub < 2; sub++) {
                #pragma unroll
                for (int jj = 0; jj < 4; jj++) {
                    const uint32_t* bf = bhf[sub] + (jj >> 1)*4 + (jj & 1)*2;
                    #pragma unroll
                    for (int i = 0; i < 4; i++) mma_f16(acc[i][jj], ah[sub][i], bf);
                }
            }
        }
    }

    // epilogue
    const int lrow = lane >> 2, lcol = (lane & 3) * 2;
    #pragma unroll
    for (int i = 0; i < 4; i++) {
        #pragma unroll
        for (int j = 0; j < 4; j++) {
            int col = n0 + wn*32 + j*8 + lcol;
            float bz0 = __ldg(bias + col), bz1 = __ldg(bias + col + 1);
            #pragma unroll
            for (int h = 0; h < 2; h++) {
                int row = m0 + wm*64 + i*16 + lrow + h*8;
                float v0 = acc[i][j][2*h]   + bz0;
                float v1 = acc[i][j][2*h+1] + bz1;
                if (EPI == 1) { v0 = gelu_tanh(v0); v1 = gelu_tanh(v1); }
                if (EPI == 2) {
                    int b = row / NP, p = row - b*NP;
                    long long base = EMB_OFF + ((long long)b*MAXE + g_sidx[b] + p)*DD + col;
                    Cf[base] = v0; Cf[base + 1] = v1;
                } else {
                    size_t o = (size_t)row * Nout + col;
                    *(__half2*)(Oh + o) = __halves2half2(__float2half_rn(v0), __float2half_rn(v1));
                }
            }
        }
    }
}

// ---------------- text rows: embed gather + attn + labels ----------------
__global__ void write_text_kernel(const int* __restrict__ ids,
                                  const int* __restrict__ mask,
                                  const int* __restrict__ labels,
                                  const float* __restrict__ table,
                                  float* __restrict__ out)
{
    int row = blockIdx.x;
    int b = row / MAXE, j = row - b*MAXE;
    int s = g_sidx[b];
    if (j >= s && j < s + NP) return;
    int tj = (j < s) ? j : j - (NP - 1);
    const float* src = table + (size_t)ids[b*SS + tj] * DD;
    float* dst = out + EMB_OFF + (size_t)row * DD;
    for (int c = threadIdx.x * 4; c < DD; c += blockDim.x * 4) {
        float4 v = *(const float4*)(src + c);
        dst[c] = v.x; dst[c+1] = v.y; dst[c+2] = v.z; dst[c+3] = v.w;
    }
    if (threadIdx.x == 0) {
        out[ATT_OFF + row] = (float)mask[b*SS + tj];
        out[LAB_OFF + row] = (float)labels[b*SS + tj];
    }
}

__global__ void fill_misc_kernel(float* __restrict__ out)
{
    long long i = (long long)blockIdx.x * blockDim.x + threadIdx.x;
    long long nz = TOTAL - RL_OFF;
    if (i < nz) out[RL_OFF + i] = 0.0f;
    if (i == 0) out[0] = 0.0f;
    if (i < (long long)BB * MAXE) {
        int b = (int)(i / MAXE), j = (int)(i - (long long)b * MAXE);
        int s = g_sidx[b];
        if (j >= s && j < s + NP) {
            out[ATT_OFF + i] = 1.0f;
            out[LAB_OFF + i] = -100.0f;
        }
    }
}

// ---------------- launch ----------------
extern "C" void kernel_launch(void* const* d_in, const int* in_sizes, int n_in,
                              void* d_out, int out_size)
{
    const int*   ids     = (const int*)  d_in[0];
    const float* px      = (const float*)d_in[1];
    const int*   mask    = (const int*)  d_in[2];
    const int*   labels  = (const int*)  d_in[3];
    const float* table   = (const float*)d_in[4];
    const float* patch_w = (const float*)d_in[6];
    const float* patch_b = (const float*)d_in[7];
    const float* w1      = (const float*)d_in[8];
    const float* b1      = (const float*)d_in[9];
    const float* w2      = (const float*)d_in[10];
    const float* b2      = (const float*)d_in[11];
    float* out = (float*)d_out;

    __half *xh, *hh, *th, *pwh, *w1h, *w2h;
    cudaGetSymbolAddress((void**)&xh,  g_xh);
    cudaGetSymbolAddress((void**)&hh,  g_hh);
    cudaGetSymbolAddress((void**)&th,  g_th);
    cudaGetSymbolAddress((void**)&pwh, g_pwt_hi);
    cudaGetSymbolAddress((void**)&w1h, g_w1t_hi);
    cudaGetSymbolAddress((void**)&w2h, g_w2t_hi);

    cudaFuncSetAttribute(gemm_mma1<0>, cudaFuncAttributeMaxDynamicSharedMemorySize, GS1);
    cudaFuncSetAttribute(gemm_mma1<1>, cudaFuncAttributeMaxDynamicSharedMemorySize, GS1);
    cudaFuncSetAttribute(gemm_mma1<2>, cudaFuncAttributeMaxDynamicSharedMemorySize, GS1);

    dim3 tb(32, 8);
    // order chosen so ncu's capture slot (empirically launch #4) lands on gemm_mma1<1> (GEMM2)
    transpose_all_kernel<<<21120, tb>>>(patch_w, w1, w2);                                 // 1
    patchify_kernel<<<(MTOT*KP1 + 255)/256, 256>>>(px);                                   // 2
    gemm_mma1<0><<<dim3(DV/128, MTOT/128), 256, GS1>>>(xh, pwh, patch_b,
                                                       nullptr, hh, KP1, DV);             // 3
    gemm_mma1<1><<<dim3(DD/128, MTOT/128), 256, GS1>>>(hh, w1h, b1,
                                                       nullptr, th, DV, DD);              // 4 (captured)
    find_sidx_kernel<<<BB, 256>>>(ids);                                                   // 5
    gemm_mma1<2><<<dim3(DD/128, MTOT/128), 256, GS1>>>(th, w2h, b2,
                                                       out, nullptr, DD, DD);             // 6
    write_text_kernel<<<BB*MAXE, 256>>>(ids, mask, labels, table, out);                   // 7

    long long nfill = TOTAL - RL_OFF;
    fill_misc_kernel<<<(int)((nfill + 255)/256), 256>>>(out);                             // 8
}

// round 16
// speedup vs baseline: 1.1458x; 1.1458x over previous
#include <cuda_runtime.h>
#include <cuda_fp16.h>
#include <cstdint>

// ---------------- problem constants ----------------
#define IMAGE_TOKEN 32000
constexpr int BB    = 8;
constexpr int SS    = 1024;
constexpr int DD    = 4096;
constexpr int DV    = 1024;
constexpr int KP1   = 640;     // 588 padded to mult of 64
constexpr int NP    = 576;
constexpr int MAXE  = 1599;
constexpr int MTOT  = 4608;    // B*NP

constexpr long long EMB_OFF = 1;
constexpr long long ATT_OFF = EMB_OFF + (long long)BB*MAXE*DD;
constexpr long long LAB_OFF = ATT_OFF + (long long)BB*MAXE;
constexpr long long RL_OFF  = LAB_OFF + (long long)BB*MAXE;
constexpr long long TOTAL   = RL_OFF + 32LL*MAXE*8 + 32LL*MAXE*2;

// ---------------- scratch (device globals) ----------------
__device__ __half g_xh[(size_t)MTOT*KP1];
__device__ __half g_hh[(size_t)MTOT*DV];
__device__ __half g_th[(size_t)MTOT*DD];
__device__ int    g_sidx[BB];
__device__ __half g_pwt_hi[(size_t)DV*KP1];
__device__ __half g_w1t_hi[(size_t)DD*DV];
__device__ __half g_w2t_hi[(size_t)DD*DD];

// ---------------- helpers ----------------
__device__ __forceinline__ uint32_t smem_u32(const void* p) {
    uint32_t a;
    asm("{ .reg .u64 t; cvta.to.shared.u64 t, %1; cvt.u32.u64 %0, t; }" : "=r"(a) : "l"(p));
    return a;
}
__device__ __forceinline__ float gelu_tanh(float x) {
    float x3 = x*x*x;
    return 0.5f*x*(1.0f + tanhf(0.7978845608028654f*(x + 0.044715f*x3)));
}

#define CP_ASYNC16(dst, src) \
    asm volatile("cp.async.cg.shared.global [%0], [%1], 16;" :: "r"(dst), "l"(src))
#define CP_COMMIT() asm volatile("cp.async.commit_group;")

template<int N>
__device__ __forceinline__ void cp_wait() {
    asm volatile("cp.async.wait_group %0;" :: "n"(N));
}

__device__ __forceinline__ void ldsm_x4(uint32_t* r, uint32_t addr) {
    asm volatile("ldmatrix.sync.aligned.m8n8.x4.shared.b16 {%0,%1,%2,%3}, [%4];"
        : "=r"(r[0]), "=r"(r[1]), "=r"(r[2]), "=r"(r[3]) : "r"(addr));
}
// non-volatile — pure register op; compiler may interleave
__device__ __forceinline__ void mma_f16(float* d, const uint32_t* a, const uint32_t* b) {
    asm("mma.sync.aligned.m16n8k16.row.col.f32.f16.f16.f32 "
        "{%0,%1,%2,%3}, {%4,%5,%6,%7}, {%8,%9}, {%0,%1,%2,%3};"
        : "+f"(d[0]), "+f"(d[1]), "+f"(d[2]), "+f"(d[3])
        : "r"(a[0]), "r"(a[1]), "r"(a[2]), "r"(a[3]), "r"(b[0]), "r"(b[1]));
}

constexpr int KCH  = 64;
constexpr int ROWB = KCH * 2;           // 128 B per smem row
constexpr int ARR  = 128 * ROWB;        // 16384 B per 128-row operand array

__device__ __forceinline__ uint32_t swz(int row, int ch) {
    return (uint32_t)(row * ROWB + ((ch ^ (row & 7)) << 4));
}

// ---------------- misc kernels ----------------
__global__ void find_sidx_kernel(const int* __restrict__ ids) {
    __shared__ int sm;
    if (threadIdx.x == 0) sm = SS;
    __syncthreads();
    int b = blockIdx.x;
    for (int t = threadIdx.x; t < SS; t += blockDim.x)
        if (ids[b*SS + t] == IMAGE_TOKEN) atomicMin(&sm, t);
    __syncthreads();
    if (threadIdx.x == 0) g_sidx[b] = sm;
}

__global__ void patchify_kernel(const float* __restrict__ px) {
    int idx = blockIdx.x*blockDim.x + threadIdx.x;
    if (idx >= MTOT*KP1) return;
    int m = idx / KP1, k = idx - m*KP1;
    float v = 0.0f;
    if (k < 588) {
        int b = m / NP, patch = m - b*NP;
        int gi = patch / 24, gj = patch - gi*24;
        int c = k / 196, r = k - c*196;
        int pi = r / 14, pj = r - pi*14;
        v = px[ (((size_t)(b*3 + c)*336) + gi*14 + pi) * 336 + gj*14 + pj ];
    }
    g_xh[idx] = __float2half_rn(v);
}

// fused transpose of all three weight matrices -> hi-only fp16, (N, Kp) layout
__global__ void transpose_all_kernel(const float* __restrict__ pw,
                                     const float* __restrict__ w1,
                                     const float* __restrict__ w2)
{
    int b = blockIdx.x;
    const float* W; __half* T; int K, N, Kp, kb;
    if (b < 640)       { W = pw; T = g_pwt_hi; K = 588; N = DV; Kp = KP1; kb = 20; }
    else if (b < 4736) { b -= 640;  W = w1; T = g_w1t_hi; K = DV; N = DD; Kp = DV; kb = 32; }
    else               { b -= 4736; W = w2; T = g_w2t_hi; K = DD; N = DD; Kp = DD; kb = 128; }
    int k0 = (b % kb) * 32, n0 = (b / kb) * 32;

    __shared__ float tile[32][33];
    int tx = threadIdx.x, ty = threadIdx.y;
    #pragma unroll
    for (int i = 0; i < 4; i++) {
        int k = k0 + ty + i*8;
        tile[ty + i*8][tx] = (k < K) ? W[(size_t)k*N + n0 + tx] : 0.0f;
    }
    __syncthreads();
    #pragma unroll
    for (int i = 0; i < 4; i++) {
        int n = n0 + ty + i*8;
        T[(size_t)n*Kp + k0 + tx] = __float2half_rn(tile[tx][ty + i*8]);
    }
}

// ---------------- 1-pass fp16 GEMM: CTA 128x128, 256 thr, warp 64x32, 2 CTAs/SM --------
// 3-stage cp.async pipeline (stage = Ah 16K | Bh 16K); fill issued after MMA group 0
// EPI: 0 = +bias -> f16 ; 1 = gelu(+bias) -> f16 ; 2 = +bias fp32 scatter to d_out
constexpr int STAGE1 = 2 * ARR;         // 32768
constexpr int GS1    = 3 * STAGE1;      // 98304

template<int EPI>
__global__ __launch_bounds__(256, 2)
void gemm_mma1(const __half* __restrict__ Ah, const __half* __restrict__ Bh,
               const float* __restrict__ bias,
               float* __restrict__ Cf, __half* __restrict__ Oh,
               int Kp, int Nout)
{
    extern __shared__ char smem[];
    const uint32_t sbase = smem_u32(smem);
    const int tid = threadIdx.x, wid = tid >> 5, lane = tid & 31;
    const int m0 = blockIdx.y * 128, n0 = blockIdx.x * 128;
    const int wm = wid >> 2, wn = wid & 3;     // warp grid 2x4, warp tile 64x32

    const int KT = Kp / KCH;

    auto fill = [&](int slot, int k0) {
        uint32_t stb = sbase + slot * STAGE1;
        #pragma unroll
        for (int u = 0; u < 4; u++) {
            int c = tid*4 + u;                 // 0..1023
            int row = c >> 3, ch = c & 7;
            uint32_t so = swz(row, ch);
            CP_ASYNC16(stb + so,       Ah + (size_t)(m0 + row)*Kp + k0 + ch*8);
            CP_ASYNC16(stb + ARR + so, Bh + (size_t)(n0 + row)*Kp + k0 + ch*8);
        }
    };

    float acc[4][4][4];
    #pragma unroll
    for (int i = 0; i < 4; i++)
        #pragma unroll
        for (int j = 0; j < 4; j++)
            #pragma unroll
            for (int r = 0; r < 4; r++) acc[i][j][r] = 0.0f;

    // per-lane ldmatrix address components (non-trans; operands stored k-contiguous)
    const int j8 = lane & 7, i4 = lane >> 3;
    const int arow_in = ((i4 & 1) << 3) + j8, achsel = i4 >> 1;
    const int brow_in = ((i4 >> 1) << 3) + j8, bchsel = i4 & 1;

    auto do_group = [&](uint32_t stb, int g) {
        uint32_t ah[4][4], bh[8];
        #pragma unroll
        for (int i = 0; i < 4; i++) {
            int row = wm*64 + i*16 + arow_in;
            ldsm_x4(ah[i], stb + swz(row, 2*g + achsel));
        }
        #pragma unroll
        for (int jp = 0; jp < 2; jp++) {
            int row = wn*32 + jp*16 + brow_in;
            ldsm_x4(bh + jp*4, stb + ARR + swz(row, 2*g + bchsel));
        }
        #pragma unroll
        for (int jj = 0; jj < 4; jj++) {
            const uint32_t* bf = bh + (jj >> 1)*4 + (jj & 1)*2;
            #pragma unroll
            for (int i = 0; i < 4; i++) mma_f16(acc[i][jj], ah[i], bf);
        }
    };

    fill(0, 0); CP_COMMIT();
    fill(1, KCH); CP_COMMIT();

    for (int ks = 0; ks < KT; ks++) {
        cp_wait<1>();
        __syncthreads();
        uint32_t stb = sbase + (ks % 3) * STAGE1;

        // group 0 first: feed the tensor queue right after the barrier...
        do_group(stb, 0);
        // ...then issue the next stage's fill while the queue drains
        int ns = ks + 2;
        if (ns < KT) { fill(ns % 3, ns * KCH); CP_COMMIT(); }
        // remaining groups
        do_group(stb, 1);
        do_group(stb, 2);
        do_group(stb, 3);
    }

    // epilogue
    const int lrow = lane >> 2, lcol = (lane & 3) * 2;
    #pragma unroll
    for (int i = 0; i < 4; i++) {
        #pragma unroll
        for (int j = 0; j < 4; j++) {
            int col = n0 + wn*32 + j*8 + lcol;
            float bz0 = __ldg(bias + col), bz1 = __ldg(bias + col + 1);
            #pragma unroll
            for (int h = 0; h < 2; h++) {
                int row = m0 + wm*64 + i*16 + lrow + h*8;
                float v0 = acc[i][j][2*h]   + bz0;
                float v1 = acc[i][j][2*h+1] + bz1;
                if (EPI == 1) { v0 = gelu_tanh(v0); v1 = gelu_tanh(v1); }
                if (EPI == 2) {
                    int b = row / NP, p = row - b*NP;
                    long long base = EMB_OFF + ((long long)b*MAXE + g_sidx[b] + p)*DD + col;
                    Cf[base] = v0; Cf[base + 1] = v1;
                } else {
                    size_t o = (size_t)row * Nout + col;
                    *(__half2*)(Oh + o) = __halves2half2(__float2half_rn(v0), __float2half_rn(v1));
                }
            }
        }
    }
}

// ---------------- merged output kernel: text rows + attn/labels + router zeros ----------
// blocks [0, BB*MAXE): per-row emb/attn/labels (text rows copy, image rows constants)
// blocks [BB*MAXE, BB*MAXE + ZBLK): zero router regions; block BB*MAXE also writes out[0]
constexpr long long NZ   = TOTAL - RL_OFF;              // 511680 router floats
constexpr int       ZBLK = (int)((NZ + 1023) / 1024);   // 256 thr x 4 floats

__global__ void write_out_kernel(const int* __restrict__ ids,
                                 const int* __restrict__ mask,
                                 const int* __restrict__ labels,
                                 const float* __restrict__ table,
                                 float* __restrict__ out)
{
    int blk = blockIdx.x;
    if (blk >= BB*MAXE) {
        // router zeros
        int zb = blk - BB*MAXE;
        if (zb == 0 && threadIdx.x == 0) out[0] = 0.0f;
        long long i = (long long)zb * 1024 + threadIdx.x * 4;
        #pragma unroll
        for (int u = 0; u < 4; u++)
            if (i + u < NZ) out[RL_OFF + i + u] = 0.0f;
        return;
    }
    int row = blk;
    int b = row / MAXE, j = row - b*MAXE;
    int s = g_sidx[b];
    if (j >= s && j < s + NP) {
        // image row: emb written by GEMM3 epilogue; set attn/labels only
        if (threadIdx.x == 0) {
            out[ATT_OFF + row] = 1.0f;
            out[LAB_OFF + row] = -100.0f;
        }
        return;
    }
    int tj = (j < s) ? j : j - (NP - 1);
    const float* src = table + (size_t)ids[b*SS + tj] * DD;
    float* dst = out + EMB_OFF + (size_t)row * DD;
    for (int c = threadIdx.x * 4; c < DD; c += blockDim.x * 4) {
        float4 v = *(const float4*)(src + c);
        dst[c] = v.x; dst[c+1] = v.y; dst[c+2] = v.z; dst[c+3] = v.w;
    }
    if (threadIdx.x == 0) {
        out[ATT_OFF + row] = (float)mask[b*SS + tj];
        out[LAB_OFF + row] = (float)labels[b*SS + tj];
    }
}

// ---------------- launch ----------------
extern "C" void kernel_launch(void* const* d_in, const int* in_sizes, int n_in,
                              void* d_out, int out_size)
{
    const int*   ids     = (const int*)  d_in[0];
    const float* px      = (const float*)d_in[1];
    const int*   mask    = (const int*)  d_in[2];
    const int*   labels  = (const int*)  d_in[3];
    const float* table   = (const float*)d_in[4];
    const float* patch_w = (const float*)d_in[6];
    const float* patch_b = (const float*)d_in[7];
    const float* w1      = (const float*)d_in[8];
    const float* b1      = (const float*)d_in[9];
    const float* w2      = (const float*)d_in[10];
    const float* b2      = (const float*)d_in[11];
    float* out = (float*)d_out;

    __half *xh, *hh, *th, *pwh, *w1h, *w2h;
    cudaGetSymbolAddress((void**)&xh,  g_xh);
    cudaGetSymbolAddress((void**)&hh,  g_hh);
    cudaGetSymbolAddress((void**)&th,  g_th);
    cudaGetSymbolAddress((void**)&pwh, g_pwt_hi);
    cudaGetSymbolAddress((void**)&w1h, g_w1t_hi);
    cudaGetSymbolAddress((void**)&w2h, g_w2t_hi);

    cudaFuncSetAttribute(gemm_mma1<0>, cudaFuncAttributeMaxDynamicSharedMemorySize, GS1);
    cudaFuncSetAttribute(gemm_mma1<1>, cudaFuncAttributeMaxDynamicSharedMemorySize, GS1);
    cudaFuncSetAttribute(gemm_mma1<2>, cudaFuncAttributeMaxDynamicSharedMemorySize, GS1);

    dim3 tb(32, 8);
    // order chosen so ncu's capture slot (empirically launch #4) lands on gemm_mma1<1> (GEMM2)
    transpose_all_kernel<<<21120, tb>>>(patch_w, w1, w2);                                 // 1
    patchify_kernel<<<(MTOT*KP1 + 255)/256, 256>>>(px);                                   // 2
    gemm_mma1<0><<<dim3(DV/128, MTOT/128), 256, GS1>>>(xh, pwh, patch_b,
                                                       nullptr, hh, KP1, DV);             // 3
    gemm_mma1<1><<<dim3(DD/128, MTOT/128), 256, GS1>>>(hh, w1h, b1,
                                                       nullptr, th, DV, DD);              // 4 (captured)
    find_sidx_kernel<<<BB, 256>>>(ids);                                                   // 5
    gemm_mma1<2><<<dim3(DD/128, MTOT/128), 256, GS1>>>(th, w2h, b2,
                                                       out, nullptr, DD, DD);             // 6
    write_out_kernel<<<BB*MAXE + ZBLK, 256>>>(ids, mask, labels, table, out);             // 7
}